// round 1
// baseline (speedup 1.0000x reference)
#include <cuda_runtime.h>
#include <cuda_bf16.h>

#define NG   2048
#define NSEG 8
#define SEGSZ (NG / NSEG)   // 256
#define NPIX (128 * 128)
#define NEAR_Z 0.3f
#define EPS_C 0.0001f

// ---------------- device scratch (no allocations allowed) ----------------
__device__ float4 d_pre_bbox[NG];   // u, v, rx, ry   (unsorted)
__device__ float4 d_pre_conic[NG];  // A, B, C, opa_eff
__device__ float4 d_pre_color[NG];  // r, g, b, depth(r)
__device__ float4 d_bbox[NG];       // sorted
__device__ float4 d_conic[NG];
__device__ float4 d_color[NG];
__device__ float4 d_part[NSEG][NPIX];  // per-segment (accum rgb, T)

__device__ __forceinline__ float sigmoidf(float x) {
    return 1.0f / (1.0f + __expf(-x));
}

// ---------------- 1. per-gaussian preprocess ----------------
__global__ void prep_kernel(const float* __restrict__ pos,
                            const float* __restrict__ rgb,
                            const float* __restrict__ opa,
                            const float* __restrict__ quat,
                            const float* __restrict__ scale,
                            const float* __restrict__ rot,
                            const float* __restrict__ tran) {
    int g = blockIdx.x * blockDim.x + threadIdx.x;
    if (g >= NG) return;

    float R00 = rot[0], R01 = rot[1], R02 = rot[2];
    float R10 = rot[3], R11 = rot[4], R12 = rot[5];
    float R20 = rot[6], R21 = rot[7], R22 = rot[8];
    float t0 = tran[0], t1 = tran[1], t2 = tran[2];

    float p0 = pos[3 * g + 0], p1 = pos[3 * g + 1], p2 = pos[3 * g + 2];
    // pos_cam = rot @ pos + tran
    float x = R00 * p0 + R01 * p1 + R02 * p2 + t0;
    float y = R10 * p0 + R11 * p1 + R12 * p2 + t1;
    float z = R20 * p0 + R21 * p1 + R22 * p2 + t2;

    float r = sqrtf(x * x + y * y + z * z);
    float iz = 1.0f / z;
    float u = x * iz, v = y * iz;

    // J rows 0,1 (row 2 not needed for 2x2 cov)
    float J00 = iz, J02 = -x * iz * iz;
    float J11 = iz, J12 = -y * iz * iz;

    // JW = J @ rot  (rows 0,1)
    float W00 = J00 * R00 + J02 * R20;
    float W01 = J00 * R01 + J02 * R21;
    float W02 = J00 * R02 + J02 * R22;
    float W10 = J11 * R10 + J12 * R20;
    float W11 = J11 * R11 + J12 * R21;
    float W12 = J11 * R12 + J12 * R22;

    // quaternion -> rotation
    float qw = quat[4 * g + 0], qx = quat[4 * g + 1];
    float qy = quat[4 * g + 2], qz = quat[4 * g + 3];
    float qn = rsqrtf(qw * qw + qx * qx + qy * qy + qz * qz);
    qw *= qn; qx *= qn; qy *= qn; qz *= qn;
    float m00 = 1.0f - 2.0f * (qy * qy + qz * qz);
    float m01 = 2.0f * (qx * qy - qw * qz);
    float m02 = 2.0f * (qx * qz + qw * qy);
    float m10 = 2.0f * (qx * qy + qw * qz);
    float m11 = 1.0f - 2.0f * (qx * qx + qz * qz);
    float m12 = 2.0f * (qy * qz - qw * qx);
    float m20 = 2.0f * (qx * qz - qw * qy);
    float m21 = 2.0f * (qy * qz + qw * qx);
    float m22 = 1.0f - 2.0f * (qx * qx + qy * qy);

    float s0 = fabsf(scale[3 * g + 0]) + 1e-4f;
    float s1 = fabsf(scale[3 * g + 1]) + 1e-4f;
    float s2 = fabsf(scale[3 * g + 2]) + 1e-4f;

    // M = Rm * diag(s)
    float M00 = m00 * s0, M01 = m01 * s1, M02 = m02 * s2;
    float M10 = m10 * s0, M11 = m11 * s1, M12 = m12 * s2;
    float M20 = m20 * s0, M21 = m21 * s1, M22 = m22 * s2;

    // cov3d = M M^T (symmetric)
    float c00 = M00 * M00 + M01 * M01 + M02 * M02;
    float c01 = M00 * M10 + M01 * M11 + M02 * M12;
    float c02 = M00 * M20 + M01 * M21 + M02 * M22;
    float c11 = M10 * M10 + M11 * M11 + M12 * M12;
    float c12 = M10 * M20 + M11 * M21 + M12 * M22;
    float c22 = M20 * M20 + M21 * M21 + M22 * M22;

    // cov2d = JW cov3d JW^T  (2x2)
    float u0 = c00 * W00 + c01 * W01 + c02 * W02;
    float u1 = c01 * W00 + c11 * W01 + c12 * W02;
    float u2 = c02 * W00 + c12 * W01 + c22 * W02;
    float a = W00 * u0 + W01 * u1 + W02 * u2 + EPS_C;
    float b = W10 * u0 + W11 * u1 + W12 * u2;
    float w0 = c00 * W10 + c01 * W11 + c02 * W12;
    float w1 = c01 * W10 + c11 * W11 + c12 * W12;
    float w2 = c02 * W10 + c12 * W11 + c22 * W12;
    float c = W10 * w0 + W11 * w1 + W12 * w2 + EPS_C;

    float det = a * c - b * b;
    float idet = 1.0f / det;
    float ia = c * idet, ib = -b * idet, ic = a * idet;

    float A = -0.5f * ia;
    float B = -ib;
    float C = -0.5f * ic;

    float op = sigmoidf(opa[g]);
    float rx, ry;
    if (z > NEAR_Z) {
        rx = 6.0f * sqrtf(a);   // power <= -18 outside (ia*a >= 1)
        ry = 6.0f * sqrtf(c);
    } else {
        op = 0.0f; rx = -1.0f; ry = -1.0f;
        A = 0.0f; B = 0.0f; C = 0.0f;
    }

    float cr = sigmoidf(rgb[3 * g + 0]);
    float cg = sigmoidf(rgb[3 * g + 1]);
    float cb = sigmoidf(rgb[3 * g + 2]);

    d_pre_bbox[g]  = make_float4(u, v, rx, ry);
    d_pre_conic[g] = make_float4(A, B, C, op);
    d_pre_color[g] = make_float4(cr, cg, cb, r);
}

// ---------------- 2. bitonic sort by depth r + gather ----------------
__global__ void sort_gather_kernel() {
    __shared__ unsigned long long sk[NG];  // 16 KB
    int t = threadIdx.x;  // 1024 threads

    for (int i = t; i < NG; i += 1024) {
        float rr = d_pre_color[i].w;  // r >= 0 always -> bit pattern monotone
        sk[i] = ((unsigned long long)__float_as_uint(rr) << 32) | (unsigned)i;
    }
    __syncthreads();

    for (int k = 2; k <= NG; k <<= 1) {
        for (int j = k >> 1; j > 0; j >>= 1) {
            int i  = ((t & ~(j - 1)) << 1) | (t & (j - 1));
            int ip = i + j;
            bool asc = ((i & k) == 0);
            unsigned long long va = sk[i], vb = sk[ip];
            bool swap = asc ? (va > vb) : (va < vb);
            if (swap) { sk[i] = vb; sk[ip] = va; }
            __syncthreads();
        }
    }

    for (int i = t; i < NG; i += 1024) {
        int idx = (int)(sk[i] & 0xffffffffu);
        d_bbox[i]  = d_pre_bbox[idx];
        d_conic[i] = d_pre_conic[idx];
        d_color[i] = d_pre_color[idx];
    }
}

// ---------------- 3. tiled render, one segment per block.y ----------------
// grid (64 tiles, NSEG segments), 256 threads = 16x16 pixel tile,
// 8 warps each covering an 8x4 pixel sub-tile for tight ballot culling.
__global__ void render_kernel() {
    __shared__ float4 sb[SEGSZ];   // bbox
    __shared__ float4 sc[SEGSZ];   // conic
    __shared__ float4 sl[SEGSZ];   // color

    int tid  = threadIdx.x;
    int seg  = blockIdx.y;
    int tile = blockIdx.x;
    int gbase = seg * SEGSZ;

    sb[tid] = d_bbox[gbase + tid];
    sc[tid] = d_conic[gbase + tid];
    sl[tid] = d_color[gbase + tid];
    __syncthreads();

    int w = tid >> 5, lane = tid & 31;
    int tx = tile & 7, ty = tile >> 3;
    int ixb = tx * 16 + ((w & 1) << 3);
    int iyb = ty * 16 + ((w >> 1) << 2);
    int ix = ixb + (lane & 7);
    int iy = iyb + (lane >> 3);

    const float inv = 1.0f / 128.0f;
    float pxf = (ix - 63.5f) * inv;
    float pyf = (iy - 63.5f) * inv;
    float wx0 = (ixb - 63.5f) * inv, wx1 = (ixb + 7 - 63.5f) * inv;
    float wy0 = (iyb - 63.5f) * inv, wy1 = (iyb + 3 - 63.5f) * inv;

    float T = 1.0f, ar = 0.0f, ag = 0.0f, ab = 0.0f;

    for (int base = 0; base < SEGSZ; base += 32) {
        float4 bb = sb[base + lane];
        bool hit = (bb.x - bb.z <= wx1) && (bb.x + bb.z >= wx0) &&
                   (bb.y - bb.w <= wy1) && (bb.y + bb.w >= wy0);
        unsigned m = __ballot_sync(0xffffffffu, hit);
        while (m) {
            int j = __ffs(m) - 1;
            m &= m - 1;
            float4 q  = sb[base + j];   // broadcast LDS
            float4 cn = sc[base + j];
            float4 cl = sl[base + j];
            float dx = pxf - q.x, dy = pyf - q.y;
            float pw = fmaf(cn.x * dx, dx, fmaf(cn.y * dx, dy, cn.z * dy * dy));
            float alpha = fminf(cn.w * __expf(pw), 0.99f);
            float wt = T * alpha;
            ar = fmaf(wt, cl.x, ar);
            ag = fmaf(wt, cl.y, ag);
            ab = fmaf(wt, cl.z, ab);
            T -= wt;  // T *= (1 - alpha)
        }
        if (__all_sync(0xffffffffu, T < 1e-7f)) break;
    }

    int p = iy * 128 + ix;
    d_part[seg][p] = make_float4(ar, ag, ab, T);
}

// ---------------- 4. combine segments front-to-back ----------------
__global__ void combine_kernel(float* __restrict__ out) {
    int p = blockIdx.x * blockDim.x + threadIdx.x;  // 0..16383
    float T = 1.0f, r = 0.0f, g = 0.0f, b = 0.0f;
#pragma unroll
    for (int s = 0; s < NSEG; s++) {
        float4 c = d_part[s][p];
        r = fmaf(T, c.x, r);
        g = fmaf(T, c.y, g);
        b = fmaf(T, c.z, b);
        T *= c.w;
    }
    out[3 * p + 0] = r;
    out[3 * p + 1] = g;
    out[3 * p + 2] = b;
}

// ---------------- launch ----------------
extern "C" void kernel_launch(void* const* d_in, const int* in_sizes, int n_in,
                              void* d_out, int out_size) {
    const float* pos   = (const float*)d_in[0];
    const float* rgb   = (const float*)d_in[1];
    const float* opa   = (const float*)d_in[2];
    const float* quat  = (const float*)d_in[3];
    const float* scale = (const float*)d_in[4];
    const float* rot   = (const float*)d_in[5];
    const float* tran  = (const float*)d_in[6];
    float* out = (float*)d_out;

    prep_kernel<<<NG / 256, 256>>>(pos, rgb, opa, quat, scale, rot, tran);
    sort_gather_kernel<<<1, 1024>>>();
    render_kernel<<<dim3(64, NSEG), 256>>>();
    combine_kernel<<<NPIX / 256, 256>>>(out);
}

// round 2
// speedup vs baseline: 1.0620x; 1.0620x over previous
#include <cuda_runtime.h>
#include <cuda_bf16.h>

#define NG   2048
#define NSEG 8
#define SEGSZ (NG / NSEG)   // 256
#define NPIX (128 * 128)
#define NEAR_Z 0.3f
#define EPS_C 0.0001f

// ---------------- device scratch (no allocations allowed) ----------------
__device__ float4 d_pre_bbox[NG];   // u, v, rx, ry   (unsorted)
__device__ float4 d_pre_conic[NG];  // A, B, C, opa_eff
__device__ float4 d_pre_color[NG];  // r, g, b, depth(r)
__device__ float4 d_bbox[NG];       // sorted
__device__ float4 d_conic[NG];
__device__ float4 d_color[NG];
__device__ float4 d_part[NSEG][NPIX];  // per-segment (accum rgb, T)

__device__ __forceinline__ float sigmoidf(float x) {
    return 1.0f / (1.0f + __expf(-x));
}

__device__ __forceinline__ unsigned long long bexch(unsigned long long v, int j,
                                                    int lane, bool asc) {
    unsigned long long o = __shfl_xor_sync(0xffffffffu, v, j);
    bool lower = ((lane & j) == 0);
    bool takeMin = (lower == asc);
    unsigned long long mn = (v < o) ? v : o;
    unsigned long long mx = (v < o) ? o : v;
    return takeMin ? mn : mx;
}

// ---------------- 1. fused prep + hybrid bitonic sort + gather ----------------
// Single block, 1024 threads. Each warp owns 64 contiguous elements in
// registers (2 per thread); strides j<=32 run via shfl (no syncs), only
// strides j>=64 hit shared memory (15 passes total vs 66 for plain bitonic).
__global__ void __launch_bounds__(1024) prep_sort_kernel(
        const float* __restrict__ pos,
        const float* __restrict__ rgb,
        const float* __restrict__ opa,
        const float* __restrict__ quat,
        const float* __restrict__ scale,
        const float* __restrict__ rot,
        const float* __restrict__ tran) {
    __shared__ unsigned long long sk[NG];  // 16 KB
    int t = threadIdx.x;

    float R00 = rot[0], R01 = rot[1], R02 = rot[2];
    float R10 = rot[3], R11 = rot[4], R12 = rot[5];
    float R20 = rot[6], R21 = rot[7], R22 = rot[8];
    float t0 = tran[0], t1 = tran[1], t2 = tran[2];

    // ---- phase A: preprocess (2 gaussians per thread) ----
    for (int g = t; g < NG; g += 1024) {
        float p0 = pos[3 * g + 0], p1 = pos[3 * g + 1], p2 = pos[3 * g + 2];
        float x = R00 * p0 + R01 * p1 + R02 * p2 + t0;
        float y = R10 * p0 + R11 * p1 + R12 * p2 + t1;
        float z = R20 * p0 + R21 * p1 + R22 * p2 + t2;

        float r = sqrtf(x * x + y * y + z * z);
        float iz = 1.0f / z;
        float u = x * iz, v = y * iz;

        float J00 = iz, J02 = -x * iz * iz;
        float J11 = iz, J12 = -y * iz * iz;

        float W00 = J00 * R00 + J02 * R20;
        float W01 = J00 * R01 + J02 * R21;
        float W02 = J00 * R02 + J02 * R22;
        float W10 = J11 * R10 + J12 * R20;
        float W11 = J11 * R11 + J12 * R21;
        float W12 = J11 * R12 + J12 * R22;

        float qw = quat[4 * g + 0], qx = quat[4 * g + 1];
        float qy = quat[4 * g + 2], qz = quat[4 * g + 3];
        float qn = rsqrtf(qw * qw + qx * qx + qy * qy + qz * qz);
        qw *= qn; qx *= qn; qy *= qn; qz *= qn;
        float m00 = 1.0f - 2.0f * (qy * qy + qz * qz);
        float m01 = 2.0f * (qx * qy - qw * qz);
        float m02 = 2.0f * (qx * qz + qw * qy);
        float m10 = 2.0f * (qx * qy + qw * qz);
        float m11 = 1.0f - 2.0f * (qx * qx + qz * qz);
        float m12 = 2.0f * (qy * qz - qw * qx);
        float m20 = 2.0f * (qx * qz - qw * qy);
        float m21 = 2.0f * (qy * qz + qw * qx);
        float m22 = 1.0f - 2.0f * (qx * qx + qy * qy);

        float s0 = fabsf(scale[3 * g + 0]) + 1e-4f;
        float s1 = fabsf(scale[3 * g + 1]) + 1e-4f;
        float s2 = fabsf(scale[3 * g + 2]) + 1e-4f;

        float M00 = m00 * s0, M01 = m01 * s1, M02 = m02 * s2;
        float M10 = m10 * s0, M11 = m11 * s1, M12 = m12 * s2;
        float M20 = m20 * s0, M21 = m21 * s1, M22 = m22 * s2;

        float c00 = M00 * M00 + M01 * M01 + M02 * M02;
        float c01 = M00 * M10 + M01 * M11 + M02 * M12;
        float c02 = M00 * M20 + M01 * M21 + M02 * M22;
        float c11 = M10 * M10 + M11 * M11 + M12 * M12;
        float c12 = M10 * M20 + M11 * M21 + M12 * M22;
        float c22 = M20 * M20 + M21 * M21 + M22 * M22;

        float u0 = c00 * W00 + c01 * W01 + c02 * W02;
        float u1 = c01 * W00 + c11 * W01 + c12 * W02;
        float u2 = c02 * W00 + c12 * W01 + c22 * W02;
        float a = W00 * u0 + W01 * u1 + W02 * u2 + EPS_C;
        float b = W10 * u0 + W11 * u1 + W12 * u2;
        float w0 = c00 * W10 + c01 * W11 + c02 * W12;
        float w1 = c01 * W10 + c11 * W11 + c12 * W12;
        float w2 = c02 * W10 + c12 * W11 + c22 * W12;
        float c = W10 * w0 + W11 * w1 + W12 * w2 + EPS_C;

        float det = a * c - b * b;
        float idet = 1.0f / det;
        float A = -0.5f * c * idet;
        float B = b * idet;          // -ib, since ib = -b/det
        float C = -0.5f * a * idet;

        float op = sigmoidf(opa[g]);
        float rx, ry;
        if (z > NEAR_Z) {
            rx = 6.0f * sqrtf(a);
            ry = 6.0f * sqrtf(c);
        } else {
            op = 0.0f; rx = -1.0f; ry = -1.0f;
            A = 0.0f; B = 0.0f; C = 0.0f;
        }

        float cr = sigmoidf(rgb[3 * g + 0]);
        float cg = sigmoidf(rgb[3 * g + 1]);
        float cb = sigmoidf(rgb[3 * g + 2]);

        d_pre_bbox[g]  = make_float4(u, v, rx, ry);
        d_pre_conic[g] = make_float4(A, B, C, op);
        d_pre_color[g] = make_float4(cr, cg, cb, r);

        sk[g] = ((unsigned long long)__float_as_uint(r) << 32) | (unsigned)g;
    }
    __syncthreads();

    // ---- phase B: hybrid bitonic sort on 64-bit keys ----
    int lane = t & 31;
    int w = t >> 5;               // 32 warps * 64 elements
    int ia = (w << 6) + lane;     // regs: a = sk[ia], b = sk[ia+32]
    int ib = ia + 32;

    unsigned long long a = sk[ia], b = sk[ib];

    // stages k = 2..64 entirely in registers
#pragma unroll
    for (int k = 2; k <= 64; k <<= 1) {
#pragma unroll
        for (int j = k >> 1; j > 0; j >>= 1) {
            if (j == 32) {  // only at k == 64: local pair (ia, ia+32)
                bool asc = ((ia & k) == 0);
                unsigned long long lo = (a < b) ? a : b;
                unsigned long long hi = (a < b) ? b : a;
                a = asc ? lo : hi;
                b = asc ? hi : lo;
            } else {
                bool asc_a = ((ia & k) == 0);
                bool asc_b = ((ib & k) == 0);
                a = bexch(a, j, lane, asc_a);
                b = bexch(b, j, lane, asc_b);
            }
        }
    }
    sk[ia] = a; sk[ib] = b;
    __syncthreads();

    // stages k = 128..2048: smem for j>=64, registers for j<=32
#pragma unroll
    for (int k = 128; k <= NG; k <<= 1) {
        for (int j = k >> 1; j >= 64; j >>= 1) {
            int i  = ((t & ~(j - 1)) << 1) | (t & (j - 1));
            int ip = i + j;
            bool asc = ((i & k) == 0);
            unsigned long long va = sk[i], vb = sk[ip];
            bool sw = asc ? (va > vb) : (va < vb);
            if (sw) { sk[i] = vb; sk[ip] = va; }
            __syncthreads();
        }
        a = sk[ia]; b = sk[ib];
        bool asc = ((ia & k) == 0);   // k >= 128: constant across the warp's 64 elems
        {   // j = 32 local step
            unsigned long long lo = (a < b) ? a : b;
            unsigned long long hi = (a < b) ? b : a;
            a = asc ? lo : hi;
            b = asc ? hi : lo;
        }
#pragma unroll
        for (int j = 16; j > 0; j >>= 1) {
            a = bexch(a, j, lane, asc);
            b = bexch(b, j, lane, asc);
        }
        sk[ia] = a; sk[ib] = b;
        __syncthreads();
    }

    // ---- phase C: gather into sorted arrays ----
    for (int i = t; i < NG; i += 1024) {
        int idx = (int)(sk[i] & 0xffffffffu);
        d_bbox[i]  = d_pre_bbox[idx];
        d_conic[i] = d_pre_conic[idx];
        d_color[i] = d_pre_color[idx];
    }
}

// ---------------- 2. tiled render, one segment per block.y ----------------
__global__ void render_kernel() {
    __shared__ float4 sb[SEGSZ];
    __shared__ float4 sc[SEGSZ];
    __shared__ float4 sl[SEGSZ];

    int tid  = threadIdx.x;
    int seg  = blockIdx.y;
    int tile = blockIdx.x;
    int gbase = seg * SEGSZ;

    sb[tid] = d_bbox[gbase + tid];
    sc[tid] = d_conic[gbase + tid];
    sl[tid] = d_color[gbase + tid];
    __syncthreads();

    int w = tid >> 5, lane = tid & 31;
    int tx = tile & 7, ty = tile >> 3;
    int ixb = tx * 16 + ((w & 1) << 3);
    int iyb = ty * 16 + ((w >> 1) << 2);
    int ix = ixb + (lane & 7);
    int iy = iyb + (lane >> 3);

    const float inv = 1.0f / 128.0f;
    float pxf = (ix - 63.5f) * inv;
    float pyf = (iy - 63.5f) * inv;
    float wx0 = (ixb - 63.5f) * inv, wx1 = (ixb + 7 - 63.5f) * inv;
    float wy0 = (iyb - 63.5f) * inv, wy1 = (iyb + 3 - 63.5f) * inv;

    float T = 1.0f, ar = 0.0f, ag = 0.0f, ab = 0.0f;

    for (int base = 0; base < SEGSZ; base += 32) {
        float4 bb = sb[base + lane];
        bool hit = (bb.x - bb.z <= wx1) && (bb.x + bb.z >= wx0) &&
                   (bb.y - bb.w <= wy1) && (bb.y + bb.w >= wy0);
        unsigned m = __ballot_sync(0xffffffffu, hit);
        while (m) {
            int j = __ffs(m) - 1;
            m &= m - 1;
            float4 q  = sb[base + j];
            float4 cn = sc[base + j];
            float4 cl = sl[base + j];
            float dx = pxf - q.x, dy = pyf - q.y;
            float pw = fmaf(cn.x * dx, dx, fmaf(cn.y * dx, dy, cn.z * dy * dy));
            float alpha = fminf(cn.w * __expf(pw), 0.99f);
            float wt = T * alpha;
            ar = fmaf(wt, cl.x, ar);
            ag = fmaf(wt, cl.y, ag);
            ab = fmaf(wt, cl.z, ab);
            T -= wt;
        }
        if (__all_sync(0xffffffffu, T < 1e-7f)) break;
    }

    int p = iy * 128 + ix;
    d_part[seg][p] = make_float4(ar, ag, ab, T);
}

// ---------------- 3. combine segments front-to-back ----------------
__global__ void __launch_bounds__(128) combine_kernel(float* __restrict__ out) {
    int p = blockIdx.x * blockDim.x + threadIdx.x;  // 0..16383

    // prefetch all segments (independent loads) before the dependent chain
    float4 c[NSEG];
#pragma unroll
    for (int s = 0; s < NSEG; s++) c[s] = d_part[s][p];

    float T = 1.0f, r = 0.0f, g = 0.0f, b = 0.0f;
#pragma unroll
    for (int s = 0; s < NSEG; s++) {
        r = fmaf(T, c[s].x, r);
        g = fmaf(T, c[s].y, g);
        b = fmaf(T, c[s].z, b);
        T *= c[s].w;
    }
    out[3 * p + 0] = r;
    out[3 * p + 1] = g;
    out[3 * p + 2] = b;
}

// ---------------- launch ----------------
extern "C" void kernel_launch(void* const* d_in, const int* in_sizes, int n_in,
                              void* d_out, int out_size) {
    const float* pos   = (const float*)d_in[0];
    const float* rgb   = (const float*)d_in[1];
    const float* opa   = (const float*)d_in[2];
    const float* quat  = (const float*)d_in[3];
    const float* scale = (const float*)d_in[4];
    const float* rot   = (const float*)d_in[5];
    const float* tran  = (const float*)d_in[6];
    float* out = (float*)d_out;

    prep_sort_kernel<<<1, 1024>>>(pos, rgb, opa, quat, scale, rot, tran);
    render_kernel<<<dim3(64, NSEG), 256>>>();
    combine_kernel<<<NPIX / 128, 128>>>(out);
}

// round 3
// speedup vs baseline: 1.2449x; 1.1722x over previous
#include <cuda_runtime.h>
#include <cuda_bf16.h>

#define NG   2048
#define NSEG 8
#define SEGSZ (NG / NSEG)   // 256
#define NPIX (128 * 128)
#define NEAR_Z 0.3f
#define EPS_C 0.0001f

#define RB 64          // rank blocks
#define RT 256         // threads per rank block
#define TPG 8          // threads per gaussian (RB*RT/TPG == NG)
#define CHUNK (NG / TPG)  // 256 comparisons per thread

// ---------------- device scratch (no allocations allowed) ----------------
__device__ float4 d_bbox[NG];          // sorted: u, v, rx, ry
__device__ float4 d_conic[NG];         // sorted: A, B, C, opa_eff
__device__ float4 d_color[NG];         // sorted: r, g, b, depth
__device__ float4 d_part[NSEG][NPIX];  // per-segment (accum rgb, T)

__device__ __forceinline__ float sigmoidf(float x) {
    return 1.0f / (1.0f + __expf(-x));
}

// ---------------- 1. fused prep + parallel rank-scatter sort ----------------
// 64 blocks x 256 threads. Each block recomputes all 2048 depth keys into
// smem (cheap), then 8 threads per gaussian brute-force its stable rank
// (256 comparisons each), reduce via shfl, and the leader thread computes
// the full projection and scatter-writes to the sorted position.
__global__ void __launch_bounds__(RT) prep_rank_kernel(
        const float* __restrict__ pos,
        const float* __restrict__ rgb,
        const float* __restrict__ opa,
        const float* __restrict__ quat,
        const float* __restrict__ scale,
        const float* __restrict__ rot,
        const float* __restrict__ tran) {
    __shared__ __align__(16) float s_r[NG];   // 8 KB depth keys
    int tid = threadIdx.x;

    float R00 = rot[0], R01 = rot[1], R02 = rot[2];
    float R10 = rot[3], R11 = rot[4], R12 = rot[5];
    float R20 = rot[6], R21 = rot[7], R22 = rot[8];
    float t0 = tran[0], t1 = tran[1], t2 = tran[2];

    // ---- phase A: all 2048 depth keys (each block, redundantly) ----
    for (int j = tid; j < NG; j += RT) {
        float p0 = pos[3 * j + 0], p1 = pos[3 * j + 1], p2 = pos[3 * j + 2];
        float x = R00 * p0 + R01 * p1 + R02 * p2 + t0;
        float y = R10 * p0 + R11 * p1 + R12 * p2 + t1;
        float z = R20 * p0 + R21 * p1 + R22 * p2 + t2;
        s_r[j] = sqrtf(x * x + y * y + z * z);
    }
    __syncthreads();

    // ---- phase B: stable rank via brute force ----
    // gaussian id for this thread group; 8 consecutive threads share one g
    int g = (blockIdx.x * RT + tid) >> 3;    // 0..2047
    int q = tid & 7;                         // sub-rank 0..7
    float rg = s_r[g];

    int cnt = 0;
    const float4* s4 = reinterpret_cast<const float4*>(s_r);
    int base = q * CHUNK;                    // this thread scans [base, base+CHUNK)
#pragma unroll 4
    for (int i = 0; i < CHUNK / 4; i++) {
        int j = base + i * 4;
        float4 v = s4[(base >> 2) + i];
        // stable: count (rj < rg) || (rj == rg && j < g)
        cnt += (v.x < rg) || (v.x == rg && (j + 0) < g);
        cnt += (v.y < rg) || (v.y == rg && (j + 1) < g);
        cnt += (v.z < rg) || (v.z == rg && (j + 2) < g);
        cnt += (v.w < rg) || (v.w == rg && (j + 3) < g);
    }
    // reduce across the 8-thread group (aligned lanes within a warp)
    cnt += __shfl_xor_sync(0xffffffffu, cnt, 1);
    cnt += __shfl_xor_sync(0xffffffffu, cnt, 2);
    cnt += __shfl_xor_sync(0xffffffffu, cnt, 4);
    int rank = cnt;

    // ---- phase C: leader thread does full projection + scatter ----
    if (q != 0) return;

    float p0 = pos[3 * g + 0], p1 = pos[3 * g + 1], p2 = pos[3 * g + 2];
    float x = R00 * p0 + R01 * p1 + R02 * p2 + t0;
    float y = R10 * p0 + R11 * p1 + R12 * p2 + t1;
    float z = R20 * p0 + R21 * p1 + R22 * p2 + t2;

    float r = sqrtf(x * x + y * y + z * z);
    float iz = 1.0f / z;
    float u = x * iz, v = y * iz;

    float J00 = iz, J02 = -x * iz * iz;
    float J11 = iz, J12 = -y * iz * iz;

    float W00 = J00 * R00 + J02 * R20;
    float W01 = J00 * R01 + J02 * R21;
    float W02 = J00 * R02 + J02 * R22;
    float W10 = J11 * R10 + J12 * R20;
    float W11 = J11 * R11 + J12 * R21;
    float W12 = J11 * R12 + J12 * R22;

    float qw = quat[4 * g + 0], qx = quat[4 * g + 1];
    float qy = quat[4 * g + 2], qz = quat[4 * g + 3];
    float qn = rsqrtf(qw * qw + qx * qx + qy * qy + qz * qz);
    qw *= qn; qx *= qn; qy *= qn; qz *= qn;
    float m00 = 1.0f - 2.0f * (qy * qy + qz * qz);
    float m01 = 2.0f * (qx * qy - qw * qz);
    float m02 = 2.0f * (qx * qz + qw * qy);
    float m10 = 2.0f * (qx * qy + qw * qz);
    float m11 = 1.0f - 2.0f * (qx * qx + qz * qz);
    float m12 = 2.0f * (qy * qz - qw * qx);
    float m20 = 2.0f * (qx * qz - qw * qy);
    float m21 = 2.0f * (qy * qz + qw * qx);
    float m22 = 1.0f - 2.0f * (qx * qx + qy * qy);

    float s0 = fabsf(scale[3 * g + 0]) + 1e-4f;
    float s1 = fabsf(scale[3 * g + 1]) + 1e-4f;
    float s2 = fabsf(scale[3 * g + 2]) + 1e-4f;

    float M00 = m00 * s0, M01 = m01 * s1, M02 = m02 * s2;
    float M10 = m10 * s0, M11 = m11 * s1, M12 = m12 * s2;
    float M20 = m20 * s0, M21 = m21 * s1, M22 = m22 * s2;

    float c00 = M00 * M00 + M01 * M01 + M02 * M02;
    float c01 = M00 * M10 + M01 * M11 + M02 * M12;
    float c02 = M00 * M20 + M01 * M21 + M02 * M22;
    float c11 = M10 * M10 + M11 * M11 + M12 * M12;
    float c12 = M10 * M20 + M11 * M21 + M12 * M22;
    float c22 = M20 * M20 + M21 * M21 + M22 * M22;

    float u0 = c00 * W00 + c01 * W01 + c02 * W02;
    float u1 = c01 * W00 + c11 * W01 + c12 * W02;
    float u2 = c02 * W00 + c12 * W01 + c22 * W02;
    float a = W00 * u0 + W01 * u1 + W02 * u2 + EPS_C;
    float b = W10 * u0 + W11 * u1 + W12 * u2;
    float w0 = c00 * W10 + c01 * W11 + c02 * W12;
    float w1 = c01 * W10 + c11 * W11 + c12 * W12;
    float w2 = c02 * W10 + c12 * W11 + c22 * W12;
    float c = W10 * w0 + W11 * w1 + W12 * w2 + EPS_C;

    float det = a * c - b * b;
    float idet = 1.0f / det;
    float A = -0.5f * c * idet;
    float B = b * idet;            // == -ib
    float C = -0.5f * a * idet;

    float op = sigmoidf(opa[g]);
    float rx, ry;
    if (z > NEAR_Z) {
        rx = 6.0f * sqrtf(a);      // power <= -18 outside (ia*a >= 1)
        ry = 6.0f * sqrtf(c);
    } else {
        op = 0.0f; rx = -1.0f; ry = -1.0f;
        A = 0.0f; B = 0.0f; C = 0.0f;
    }

    float cr = sigmoidf(rgb[3 * g + 0]);
    float cg = sigmoidf(rgb[3 * g + 1]);
    float cb = sigmoidf(rgb[3 * g + 2]);

    d_bbox[rank]  = make_float4(u, v, rx, ry);
    d_conic[rank] = make_float4(A, B, C, op);
    d_color[rank] = make_float4(cr, cg, cb, r);
}

// ---------------- 2. tiled render, one segment per block.y ----------------
__global__ void render_kernel() {
    __shared__ float4 sb[SEGSZ];
    __shared__ float4 sc[SEGSZ];
    __shared__ float4 sl[SEGSZ];

    int tid  = threadIdx.x;
    int seg  = blockIdx.y;
    int tile = blockIdx.x;
    int gbase = seg * SEGSZ;

    sb[tid] = d_bbox[gbase + tid];
    sc[tid] = d_conic[gbase + tid];
    sl[tid] = d_color[gbase + tid];
    __syncthreads();

    int w = tid >> 5, lane = tid & 31;
    int tx = tile & 7, ty = tile >> 3;
    int ixb = tx * 16 + ((w & 1) << 3);
    int iyb = ty * 16 + ((w >> 1) << 2);
    int ix = ixb + (lane & 7);
    int iy = iyb + (lane >> 3);

    const float inv = 1.0f / 128.0f;
    float pxf = (ix - 63.5f) * inv;
    float pyf = (iy - 63.5f) * inv;
    float wx0 = (ixb - 63.5f) * inv, wx1 = (ixb + 7 - 63.5f) * inv;
    float wy0 = (iyb - 63.5f) * inv, wy1 = (iyb + 3 - 63.5f) * inv;

    float T = 1.0f, ar = 0.0f, ag = 0.0f, ab = 0.0f;

    for (int base = 0; base < SEGSZ; base += 32) {
        float4 bb = sb[base + lane];
        bool hit = (bb.x - bb.z <= wx1) && (bb.x + bb.z >= wx0) &&
                   (bb.y - bb.w <= wy1) && (bb.y + bb.w >= wy0);
        unsigned m = __ballot_sync(0xffffffffu, hit);
        while (m) {
            int j = __ffs(m) - 1;
            m &= m - 1;
            float4 qv = sb[base + j];
            float4 cn = sc[base + j];
            float4 cl = sl[base + j];
            float dx = pxf - qv.x, dy = pyf - qv.y;
            float pw = fmaf(cn.x * dx, dx, fmaf(cn.y * dx, dy, cn.z * dy * dy));
            float alpha = fminf(cn.w * __expf(pw), 0.99f);
            float wt = T * alpha;
            ar = fmaf(wt, cl.x, ar);
            ag = fmaf(wt, cl.y, ag);
            ab = fmaf(wt, cl.z, ab);
            T -= wt;
        }
        if (__all_sync(0xffffffffu, T < 1e-7f)) break;
    }

    int p = iy * 128 + ix;
    d_part[seg][p] = make_float4(ar, ag, ab, T);
}

// ---------------- 3. combine segments front-to-back ----------------
__global__ void __launch_bounds__(128) combine_kernel(float* __restrict__ out) {
    int p = blockIdx.x * blockDim.x + threadIdx.x;  // 0..16383

    float4 c[NSEG];
#pragma unroll
    for (int s = 0; s < NSEG; s++) c[s] = d_part[s][p];

    float T = 1.0f, r = 0.0f, g = 0.0f, b = 0.0f;
#pragma unroll
    for (int s = 0; s < NSEG; s++) {
        r = fmaf(T, c[s].x, r);
        g = fmaf(T, c[s].y, g);
        b = fmaf(T, c[s].z, b);
        T *= c[s].w;
    }
    out[3 * p + 0] = r;
    out[3 * p + 1] = g;
    out[3 * p + 2] = b;
}

// ---------------- launch ----------------
extern "C" void kernel_launch(void* const* d_in, const int* in_sizes, int n_in,
                              void* d_out, int out_size) {
    const float* pos   = (const float*)d_in[0];
    const float* rgb   = (const float*)d_in[1];
    const float* opa   = (const float*)d_in[2];
    const float* quat  = (const float*)d_in[3];
    const float* scale = (const float*)d_in[4];
    const float* rot   = (const float*)d_in[5];
    const float* tran  = (const float*)d_in[6];
    float* out = (float*)d_out;

    prep_rank_kernel<<<RB, RT>>>(pos, rgb, opa, quat, scale, rot, tran);
    render_kernel<<<dim3(64, NSEG), 256>>>();
    combine_kernel<<<NPIX / 128, 128>>>(out);
}

// round 4
// speedup vs baseline: 1.6294x; 1.3088x over previous
#include <cuda_runtime.h>
#include <cuda_bf16.h>

#define NG   2048
#define NSEG 8
#define SEGSZ (NG / NSEG)   // 256
#define NPIX (128 * 128)
#define NEAR_Z 0.3f
#define EPS_C 0.0001f

#define RB 64          // rank blocks
#define RT 256         // threads per rank block
#define TPG 8          // threads per gaussian
#define NF4 (NG / 4)   // 512 float4 keys

// ---------------- device scratch (no allocations allowed) ----------------
__device__ float  d_key[NG];           // depth keys
__device__ float4 d_bbox[NG];          // sorted: u, v, rx, ry
__device__ float4 d_conic[NG];         // sorted: A, B, C, opa_eff
__device__ float4 d_color[NG];         // sorted: r, g, b, depth
__device__ float4 d_part[NSEG][NPIX];  // per-segment (accum rgb, T)

__device__ __forceinline__ float sigmoidf(float x) {
    return 1.0f / (1.0f + __expf(-x));
}

// ---------------- 0. depth keys (once) ----------------
__global__ void __launch_bounds__(256) key_kernel(
        const float* __restrict__ pos,
        const float* __restrict__ rot,
        const float* __restrict__ tran) {
    int g = blockIdx.x * 256 + threadIdx.x;
    float R00 = rot[0], R01 = rot[1], R02 = rot[2];
    float R10 = rot[3], R11 = rot[4], R12 = rot[5];
    float R20 = rot[6], R21 = rot[7], R22 = rot[8];
    float t0 = tran[0], t1 = tran[1], t2 = tran[2];
    float p0 = pos[3 * g + 0], p1 = pos[3 * g + 1], p2 = pos[3 * g + 2];
    float x = R00 * p0 + R01 * p1 + R02 * p2 + t0;
    float y = R10 * p0 + R11 * p1 + R12 * p2 + t1;
    float z = R20 * p0 + R21 * p1 + R22 * p2 + t2;
    d_key[g] = sqrtf(x * x + y * y + z * z);
}

// ---------------- 1. rank + prep + scatter ----------------
// 64 blocks x 256 threads; 8 threads per gaussian. Keys loaded coalesced
// from L2 into smem; each thread scans an INTERLEAVED set of float4s so
// lanes 0..7 touch consecutive 16B chunks (conflict-free, broadcast above).
__global__ void __launch_bounds__(RT) prep_rank_kernel(
        const float* __restrict__ pos,
        const float* __restrict__ rgb,
        const float* __restrict__ opa,
        const float* __restrict__ quat,
        const float* __restrict__ scale,
        const float* __restrict__ rot,
        const float* __restrict__ tran) {
    __shared__ __align__(16) float s_r[NG];   // 8 KB
    int tid = threadIdx.x;

    // coalesced key load: 2 float4 per thread
    {
        const float4* k4 = reinterpret_cast<const float4*>(d_key);
        float4* s4w = reinterpret_cast<float4*>(s_r);
        s4w[tid]        = k4[tid];
        s4w[tid + 256]  = k4[tid + 256];
    }
    __syncthreads();

    int g = (blockIdx.x * RT + tid) >> 3;    // 0..2047
    int q = tid & 7;                         // sub-rank
    float rg = s_r[g];

    int cnt = 0;
    const float4* s4 = reinterpret_cast<const float4*>(s_r);
#pragma unroll 8
    for (int i = 0; i < NF4 / TPG; i++) {    // 64 iterations
        int f = i * TPG + q;                 // interleaved float4 index
        int j = f * 4;
        float4 v = s4[f];
        cnt += (v.x < rg) || (v.x == rg && (j + 0) < g);
        cnt += (v.y < rg) || (v.y == rg && (j + 1) < g);
        cnt += (v.z < rg) || (v.z == rg && (j + 2) < g);
        cnt += (v.w < rg) || (v.w == rg && (j + 3) < g);
    }
    cnt += __shfl_xor_sync(0xffffffffu, cnt, 1);
    cnt += __shfl_xor_sync(0xffffffffu, cnt, 2);
    cnt += __shfl_xor_sync(0xffffffffu, cnt, 4);
    int rank = cnt;

    if (q != 0) return;

    // ---- leader: full projection + scatter to sorted position ----
    float R00 = rot[0], R01 = rot[1], R02 = rot[2];
    float R10 = rot[3], R11 = rot[4], R12 = rot[5];
    float R20 = rot[6], R21 = rot[7], R22 = rot[8];
    float t0 = tran[0], t1 = tran[1], t2 = tran[2];

    float p0 = pos[3 * g + 0], p1 = pos[3 * g + 1], p2 = pos[3 * g + 2];
    float x = R00 * p0 + R01 * p1 + R02 * p2 + t0;
    float y = R10 * p0 + R11 * p1 + R12 * p2 + t1;
    float z = R20 * p0 + R21 * p1 + R22 * p2 + t2;

    float r = rg;
    float iz = 1.0f / z;
    float u = x * iz, v = y * iz;

    float J00 = iz, J02 = -x * iz * iz;
    float J11 = iz, J12 = -y * iz * iz;

    float W00 = J00 * R00 + J02 * R20;
    float W01 = J00 * R01 + J02 * R21;
    float W02 = J00 * R02 + J02 * R22;
    float W10 = J11 * R10 + J12 * R20;
    float W11 = J11 * R11 + J12 * R21;
    float W12 = J11 * R12 + J12 * R22;

    float qw = quat[4 * g + 0], qx = quat[4 * g + 1];
    float qy = quat[4 * g + 2], qz = quat[4 * g + 3];
    float qn = rsqrtf(qw * qw + qx * qx + qy * qy + qz * qz);
    qw *= qn; qx *= qn; qy *= qn; qz *= qn;
    float m00 = 1.0f - 2.0f * (qy * qy + qz * qz);
    float m01 = 2.0f * (qx * qy - qw * qz);
    float m02 = 2.0f * (qx * qz + qw * qy);
    float m10 = 2.0f * (qx * qy + qw * qz);
    float m11 = 1.0f - 2.0f * (qx * qx + qz * qz);
    float m12 = 2.0f * (qy * qz - qw * qx);
    float m20 = 2.0f * (qx * qz - qw * qy);
    float m21 = 2.0f * (qy * qz + qw * qx);
    float m22 = 1.0f - 2.0f * (qx * qx + qy * qy);

    float s0 = fabsf(scale[3 * g + 0]) + 1e-4f;
    float s1 = fabsf(scale[3 * g + 1]) + 1e-4f;
    float s2 = fabsf(scale[3 * g + 2]) + 1e-4f;

    float M00 = m00 * s0, M01 = m01 * s1, M02 = m02 * s2;
    float M10 = m10 * s0, M11 = m11 * s1, M12 = m12 * s2;
    float M20 = m20 * s0, M21 = m21 * s1, M22 = m22 * s2;

    float c00 = M00 * M00 + M01 * M01 + M02 * M02;
    float c01 = M00 * M10 + M01 * M11 + M02 * M12;
    float c02 = M00 * M20 + M01 * M21 + M02 * M22;
    float c11 = M10 * M10 + M11 * M11 + M12 * M12;
    float c12 = M10 * M20 + M11 * M21 + M12 * M22;
    float c22 = M20 * M20 + M21 * M21 + M22 * M22;

    float u0 = c00 * W00 + c01 * W01 + c02 * W02;
    float u1 = c01 * W00 + c11 * W01 + c12 * W02;
    float u2 = c02 * W00 + c12 * W01 + c22 * W02;
    float a = W00 * u0 + W01 * u1 + W02 * u2 + EPS_C;
    float b = W10 * u0 + W11 * u1 + W12 * u2;
    float w0 = c00 * W10 + c01 * W11 + c02 * W12;
    float w1 = c01 * W10 + c11 * W11 + c12 * W12;
    float w2 = c02 * W10 + c12 * W11 + c22 * W12;
    float c = W10 * w0 + W11 * w1 + W12 * w2 + EPS_C;

    float det = a * c - b * b;
    float idet = 1.0f / det;
    float A = -0.5f * c * idet;
    float B = b * idet;            // == -ib
    float C = -0.5f * a * idet;

    float op = sigmoidf(opa[g]);
    float rx, ry;
    if (z > NEAR_Z) {
        rx = 6.0f * sqrtf(a);      // power <= -18 outside (ia*a >= 1)
        ry = 6.0f * sqrtf(c);
    } else {
        op = 0.0f; rx = -1.0f; ry = -1.0f;
        A = 0.0f; B = 0.0f; C = 0.0f;
    }

    float cr = sigmoidf(rgb[3 * g + 0]);
    float cg = sigmoidf(rgb[3 * g + 1]);
    float cb = sigmoidf(rgb[3 * g + 2]);

    d_bbox[rank]  = make_float4(u, v, rx, ry);
    d_conic[rank] = make_float4(A, B, C, op);
    d_color[rank] = make_float4(cr, cg, cb, r);
}

// ---------------- 2. tiled render, one segment per block.y ----------------
__global__ void render_kernel() {
    __shared__ float4 sb[SEGSZ];
    __shared__ float4 sc[SEGSZ];
    __shared__ float4 sl[SEGSZ];

    int tid  = threadIdx.x;
    int seg  = blockIdx.y;
    int tile = blockIdx.x;
    int gbase = seg * SEGSZ;

    sb[tid] = d_bbox[gbase + tid];
    sc[tid] = d_conic[gbase + tid];
    sl[tid] = d_color[gbase + tid];
    __syncthreads();

    int w = tid >> 5, lane = tid & 31;
    int tx = tile & 7, ty = tile >> 3;
    int ixb = tx * 16 + ((w & 1) << 3);
    int iyb = ty * 16 + ((w >> 1) << 2);
    int ix = ixb + (lane & 7);
    int iy = iyb + (lane >> 3);

    const float inv = 1.0f / 128.0f;
    float pxf = (ix - 63.5f) * inv;
    float pyf = (iy - 63.5f) * inv;
    float wx0 = (ixb - 63.5f) * inv, wx1 = (ixb + 7 - 63.5f) * inv;
    float wy0 = (iyb - 63.5f) * inv, wy1 = (iyb + 3 - 63.5f) * inv;

    float T = 1.0f, ar = 0.0f, ag = 0.0f, ab = 0.0f;

    for (int base = 0; base < SEGSZ; base += 32) {
        float4 bb = sb[base + lane];
        bool hit = (bb.x - bb.z <= wx1) && (bb.x + bb.z >= wx0) &&
                   (bb.y - bb.w <= wy1) && (bb.y + bb.w >= wy0);
        unsigned m = __ballot_sync(0xffffffffu, hit);
        while (m) {
            int j = __ffs(m) - 1;
            m &= m - 1;
            float4 qv = sb[base + j];
            float4 cn = sc[base + j];
            float4 cl = sl[base + j];
            float dx = pxf - qv.x, dy = pyf - qv.y;
            float pw = fmaf(cn.x * dx, dx, fmaf(cn.y * dx, dy, cn.z * dy * dy));
            float alpha = fminf(cn.w * __expf(pw), 0.99f);
            float wt = T * alpha;
            ar = fmaf(wt, cl.x, ar);
            ag = fmaf(wt, cl.y, ag);
            ab = fmaf(wt, cl.z, ab);
            T -= wt;
        }
        if (__all_sync(0xffffffffu, T < 1e-7f)) break;
    }

    int p = iy * 128 + ix;
    d_part[seg][p] = make_float4(ar, ag, ab, T);
}

// ---------------- 3. combine segments front-to-back ----------------
__global__ void __launch_bounds__(128) combine_kernel(float* __restrict__ out) {
    int p = blockIdx.x * blockDim.x + threadIdx.x;  // 0..16383

    float4 c[NSEG];
#pragma unroll
    for (int s = 0; s < NSEG; s++) c[s] = d_part[s][p];

    float T = 1.0f, r = 0.0f, g = 0.0f, b = 0.0f;
#pragma unroll
    for (int s = 0; s < NSEG; s++) {
        r = fmaf(T, c[s].x, r);
        g = fmaf(T, c[s].y, g);
        b = fmaf(T, c[s].z, b);
        T *= c[s].w;
    }
    out[3 * p + 0] = r;
    out[3 * p + 1] = g;
    out[3 * p + 2] = b;
}

// ---------------- launch ----------------
extern "C" void kernel_launch(void* const* d_in, const int* in_sizes, int n_in,
                              void* d_out, int out_size) {
    const float* pos   = (const float*)d_in[0];
    const float* rgb   = (const float*)d_in[1];
    const float* opa   = (const float*)d_in[2];
    const float* quat  = (const float*)d_in[3];
    const float* scale = (const float*)d_in[4];
    const float* rot   = (const float*)d_in[5];
    const float* tran  = (const float*)d_in[6];
    float* out = (float*)d_out;

    key_kernel<<<NG / 256, 256>>>(pos, rot, tran);
    prep_rank_kernel<<<RB, RT>>>(pos, rgb, opa, quat, scale, rot, tran);
    render_kernel<<<dim3(64, NSEG), 256>>>();
    combine_kernel<<<NPIX / 128, 128>>>(out);
}

// round 6
// speedup vs baseline: 1.6514x; 1.0135x over previous
#include <cstdint>
#include <cuda_runtime.h>
#include <cuda_bf16.h>

#define NG   2048
#define NSEG 8
#define SEGSZ (NG / NSEG)   // 256
#define NPIX (128 * 128)
#define NEAR_Z 0.3f
#define EPS_C 0.0001f

#define RB 64          // rank blocks
#define RT 256         // threads per rank block
#define TPG 8          // threads per gaussian
#define NF4 (NG / 4)   // 512 float4 keys

// ---------------- device scratch (no allocations allowed) ----------------
__device__ float  d_key[NG];           // depth keys
__device__ float4 d_bbox[NG];          // sorted: u, v, rx, ry
__device__ float4 d_conic[NG];         // sorted: A, B, C, opa_eff
__device__ float4 d_color[NG];         // sorted: r, g, b, depth

__device__ __forceinline__ float sigmoidf(float x) {
    return 1.0f / (1.0f + __expf(-x));
}

// ---------------- 0. depth keys (once) ----------------
__global__ void __launch_bounds__(256) key_kernel(
        const float* __restrict__ pos,
        const float* __restrict__ rot,
        const float* __restrict__ tran) {
    int g = blockIdx.x * 256 + threadIdx.x;
    float R00 = rot[0], R01 = rot[1], R02 = rot[2];
    float R10 = rot[3], R11 = rot[4], R12 = rot[5];
    float R20 = rot[6], R21 = rot[7], R22 = rot[8];
    float t0 = tran[0], t1 = tran[1], t2 = tran[2];
    float p0 = pos[3 * g + 0], p1 = pos[3 * g + 1], p2 = pos[3 * g + 2];
    float x = R00 * p0 + R01 * p1 + R02 * p2 + t0;
    float y = R10 * p0 + R11 * p1 + R12 * p2 + t1;
    float z = R20 * p0 + R21 * p1 + R22 * p2 + t2;
    d_key[g] = sqrtf(x * x + y * y + z * z);
}

// ---------------- 1. rank + prep + scatter ----------------
__global__ void __launch_bounds__(RT) prep_rank_kernel(
        const float* __restrict__ pos,
        const float* __restrict__ rgb,
        const float* __restrict__ opa,
        const float* __restrict__ quat,
        const float* __restrict__ scale,
        const float* __restrict__ rot,
        const float* __restrict__ tran) {
    __shared__ __align__(16) float s_r[NG];   // 8 KB
    int tid = threadIdx.x;

    {
        const float4* k4 = reinterpret_cast<const float4*>(d_key);
        float4* s4w = reinterpret_cast<float4*>(s_r);
        s4w[tid]       = k4[tid];
        s4w[tid + 256] = k4[tid + 256];
    }
    __syncthreads();

    int g = (blockIdx.x * RT + tid) >> 3;
    int q = tid & 7;
    float rg = s_r[g];

    int cnt = 0;
    const float4* s4 = reinterpret_cast<const float4*>(s_r);
#pragma unroll 8
    for (int i = 0; i < NF4 / TPG; i++) {
        int f = i * TPG + q;                 // interleaved: lanes hit consecutive 16B
        int j = f * 4;
        float4 v = s4[f];
        cnt += (v.x < rg) || (v.x == rg && (j + 0) < g);
        cnt += (v.y < rg) || (v.y == rg && (j + 1) < g);
        cnt += (v.z < rg) || (v.z == rg && (j + 2) < g);
        cnt += (v.w < rg) || (v.w == rg && (j + 3) < g);
    }
    cnt += __shfl_xor_sync(0xffffffffu, cnt, 1);
    cnt += __shfl_xor_sync(0xffffffffu, cnt, 2);
    cnt += __shfl_xor_sync(0xffffffffu, cnt, 4);
    int rank = cnt;

    if (q != 0) return;

    float R00 = rot[0], R01 = rot[1], R02 = rot[2];
    float R10 = rot[3], R11 = rot[4], R12 = rot[5];
    float R20 = rot[6], R21 = rot[7], R22 = rot[8];
    float t0 = tran[0], t1 = tran[1], t2 = tran[2];

    float p0 = pos[3 * g + 0], p1 = pos[3 * g + 1], p2 = pos[3 * g + 2];
    float x = R00 * p0 + R01 * p1 + R02 * p2 + t0;
    float y = R10 * p0 + R11 * p1 + R12 * p2 + t1;
    float z = R20 * p0 + R21 * p1 + R22 * p2 + t2;

    float r = rg;
    float iz = 1.0f / z;
    float u = x * iz, v = y * iz;

    float J00 = iz, J02 = -x * iz * iz;
    float J11 = iz, J12 = -y * iz * iz;

    float W00 = J00 * R00 + J02 * R20;
    float W01 = J00 * R01 + J02 * R21;
    float W02 = J00 * R02 + J02 * R22;
    float W10 = J11 * R10 + J12 * R20;
    float W11 = J11 * R11 + J12 * R21;
    float W12 = J11 * R12 + J12 * R22;

    float qw = quat[4 * g + 0], qx = quat[4 * g + 1];
    float qy = quat[4 * g + 2], qz = quat[4 * g + 3];
    float qn = rsqrtf(qw * qw + qx * qx + qy * qy + qz * qz);
    qw *= qn; qx *= qn; qy *= qn; qz *= qn;
    float m00 = 1.0f - 2.0f * (qy * qy + qz * qz);
    float m01 = 2.0f * (qx * qy - qw * qz);
    float m02 = 2.0f * (qx * qz + qw * qy);
    float m10 = 2.0f * (qx * qy + qw * qz);
    float m11 = 1.0f - 2.0f * (qx * qx + qz * qz);
    float m12 = 2.0f * (qy * qz - qw * qx);
    float m20 = 2.0f * (qx * qz - qw * qy);
    float m21 = 2.0f * (qy * qz + qw * qx);
    float m22 = 1.0f - 2.0f * (qx * qx + qy * qy);

    float s0 = fabsf(scale[3 * g + 0]) + 1e-4f;
    float s1 = fabsf(scale[3 * g + 1]) + 1e-4f;
    float s2 = fabsf(scale[3 * g + 2]) + 1e-4f;

    float M00 = m00 * s0, M01 = m01 * s1, M02 = m02 * s2;
    float M10 = m10 * s0, M11 = m11 * s1, M12 = m12 * s2;
    float M20 = m20 * s0, M21 = m21 * s1, M22 = m22 * s2;

    float c00 = M00 * M00 + M01 * M01 + M02 * M02;
    float c01 = M00 * M10 + M01 * M11 + M02 * M12;
    float c02 = M00 * M20 + M01 * M21 + M02 * M22;
    float c11 = M10 * M10 + M11 * M11 + M12 * M12;
    float c12 = M10 * M20 + M11 * M21 + M12 * M22;
    float c22 = M20 * M20 + M21 * M21 + M22 * M22;

    float u0 = c00 * W00 + c01 * W01 + c02 * W02;
    float u1 = c01 * W00 + c11 * W01 + c12 * W02;
    float u2 = c02 * W00 + c12 * W01 + c22 * W02;
    float a = W00 * u0 + W01 * u1 + W02 * u2 + EPS_C;
    float b = W10 * u0 + W11 * u1 + W12 * u2;
    float w0 = c00 * W10 + c01 * W11 + c02 * W12;
    float w1 = c01 * W10 + c11 * W11 + c12 * W12;
    float w2 = c02 * W10 + c12 * W11 + c22 * W12;
    float c = W10 * w0 + W11 * w1 + W12 * w2 + EPS_C;

    float det = a * c - b * b;
    float idet = 1.0f / det;
    float A = -0.5f * c * idet;
    float B = b * idet;            // == -ib
    float C = -0.5f * a * idet;

    float op = sigmoidf(opa[g]);
    float rx, ry;
    if (z > NEAR_Z) {
        rx = 6.0f * sqrtf(a);      // power <= -18 outside
        ry = 6.0f * sqrtf(c);
    } else {
        op = 0.0f; rx = -1.0f; ry = -1.0f;
        A = 0.0f; B = 0.0f; C = 0.0f;
    }

    float cr = sigmoidf(rgb[3 * g + 0]);
    float cg = sigmoidf(rgb[3 * g + 1]);
    float cb = sigmoidf(rgb[3 * g + 2]);

    d_bbox[rank]  = make_float4(u, v, rx, ry);
    d_conic[rank] = make_float4(A, B, C, op);
    d_color[rank] = make_float4(cr, cg, cb, r);
}

// ---------------- 2. fused render + cluster combine ----------------
// Cluster of 8 CTAs = 8 depth segments of ONE 16x16 tile. Each CTA renders
// its segment into s_part[256] (per-pixel rgb,T), cluster.sync, then CTA
// rank r combines pixels [32r,32r+32) reading peers' partials over DSMEM.
__device__ __forceinline__ uint32_t smem_u32(const void* p) {
    uint32_t a;
    asm("{ .reg .u64 t; cvta.to.shared.u64 t, %1; cvt.u32.u64 %0, t; }"
        : "=r"(a) : "l"(p));
    return a;
}

__global__ void __launch_bounds__(256) __cluster_dims__(8, 1, 1)
render_kernel(float* __restrict__ out) {
    __shared__ float4 sb[SEGSZ];
    __shared__ float4 sc[SEGSZ];
    __shared__ float4 sl[SEGSZ];
    __shared__ float4 s_part[256];   // this segment's partials for the tile

    int tid  = threadIdx.x;
    int bx   = blockIdx.x;      // 0..511
    int tile = bx >> 3;         // 64 tiles
    int seg  = bx & 7;          // == cluster rank
    int gbase = seg * SEGSZ;

    sb[tid] = d_bbox[gbase + tid];
    sc[tid] = d_conic[gbase + tid];
    sl[tid] = d_color[gbase + tid];
    __syncthreads();

    int w = tid >> 5, lane = tid & 31;
    int tx = tile & 7, ty = tile >> 3;
    int lxb = (w & 1) << 3;          // local window origin in tile
    int lyb = (w >> 1) << 2;
    int lx = lxb + (lane & 7);
    int ly = lyb + (lane >> 3);
    int ix = tx * 16 + lx;
    int iy = ty * 16 + ly;

    const float inv = 1.0f / 128.0f;
    float pxf = (ix - 63.5f) * inv;
    float pyf = (iy - 63.5f) * inv;
    float wx0 = (tx * 16 + lxb - 63.5f) * inv, wx1 = wx0 + 7.0f * inv;
    float wy0 = (ty * 16 + lyb - 63.5f) * inv, wy1 = wy0 + 3.0f * inv;

    float T = 1.0f, ar = 0.0f, ag = 0.0f, ab = 0.0f;

    for (int base = 0; base < SEGSZ; base += 32) {
        float4 bb = sb[base + lane];
        bool hit = (bb.x - bb.z <= wx1) && (bb.x + bb.z >= wx0) &&
                   (bb.y - bb.w <= wy1) && (bb.y + bb.w >= wy0);
        unsigned m = __ballot_sync(0xffffffffu, hit);
        while (m) {
            int j = __ffs(m) - 1;
            m &= m - 1;
            float4 qv = sb[base + j];
            float4 cn = sc[base + j];
            float4 cl = sl[base + j];
            float dx = pxf - qv.x, dy = pyf - qv.y;
            float pw = fmaf(cn.x * dx, dx, fmaf(cn.y * dx, dy, cn.z * dy * dy));
            float alpha = fminf(cn.w * __expf(pw), 0.99f);
            float wt = T * alpha;
            ar = fmaf(wt, cl.x, ar);
            ag = fmaf(wt, cl.y, ag);
            ab = fmaf(wt, cl.z, ab);
            T -= wt;
        }
        if (__all_sync(0xffffffffu, T < 1e-7f)) break;
    }

    s_part[ly * 16 + lx] = make_float4(ar, ag, ab, T);

    // ---- cluster barrier: all segments' partials visible ----
    asm volatile("barrier.cluster.arrive.aligned;" ::: "memory");
    asm volatile("barrier.cluster.wait.aligned;" ::: "memory");

    // ---- combine: 8 lanes per pixel, one peer segment each ----
    int tseg = tid & 7;                 // which peer segment this lane reads
    int pl   = seg * 32 + (tid >> 3);   // pixel handled by this CTA's slice

    uint32_t laddr = smem_u32(&s_part[pl]);
    uint32_t paddr;
    asm("mapa.shared::cluster.u32 %0, %1, %2;" : "=r"(paddr)
        : "r"(laddr), "r"(tseg));
    float cr_, cg_, cb_, ct_;
    asm volatile("ld.shared::cluster.v4.f32 {%0,%1,%2,%3}, [%4];"
                 : "=f"(cr_), "=f"(cg_), "=f"(cb_), "=f"(ct_) : "r"(paddr));

    // exclusive product-scan of T over the 8 seg-lanes (front-to-back)
    float tp = ct_;
#pragma unroll
    for (int d = 1; d < 8; d <<= 1) {
        float v = __shfl_up_sync(0xffffffffu, tp, d, 8);
        if ((tid & 7) >= d) tp *= v;
    }
    float texcl = __shfl_up_sync(0xffffffffu, tp, 1, 8);
    if (tseg == 0) texcl = 1.0f;

    float orr = texcl * cr_, og = texcl * cg_, ob = texcl * cb_;
#pragma unroll
    for (int d = 1; d < 8; d <<= 1) {
        orr += __shfl_xor_sync(0xffffffffu, orr, d, 8);
        og  += __shfl_xor_sync(0xffffffffu, og,  d, 8);
        ob  += __shfl_xor_sync(0xffffffffu, ob,  d, 8);
    }

    if (tseg == 0) {
        int gx = tx * 16 + (pl & 15);
        int gy = ty * 16 + (pl >> 4);
        int o = 3 * (gy * 128 + gx);
        out[o + 0] = orr;
        out[o + 1] = og;
        out[o + 2] = ob;
    }

    // don't exit while peers may still be reading our s_part
    asm volatile("barrier.cluster.arrive.aligned;" ::: "memory");
    asm volatile("barrier.cluster.wait.aligned;" ::: "memory");
}

// ---------------- launch ----------------
extern "C" void kernel_launch(void* const* d_in, const int* in_sizes, int n_in,
                              void* d_out, int out_size) {
    const float* pos   = (const float*)d_in[0];
    const float* rgb   = (const float*)d_in[1];
    const float* opa   = (const float*)d_in[2];
    const float* quat  = (const float*)d_in[3];
    const float* scale = (const float*)d_in[4];
    const float* rot   = (const float*)d_in[5];
    const float* tran  = (const float*)d_in[6];
    float* out = (float*)d_out;

    key_kernel<<<NG / 256, 256>>>(pos, rot, tran);
    prep_rank_kernel<<<RB, RT>>>(pos, rgb, opa, quat, scale, rot, tran);
    render_kernel<<<512, 256>>>(out);
}